// round 6
// baseline (speedup 1.0000x reference)
#include <cuda_runtime.h>
#include <math.h>

// SpikingLayer — bit-exact replication attempt of the JAX/XLA reference.
//
// Measured r4: rel_err 4.06e-3 with an analytically-exact IIR formulation.
// Post-mortem: the error floor is the REFERENCE's own fp32 rounding (floor()
// flips cascade through the refractory feedback). Only replicating the
// reference's rounding sequence can pass 1e-3. This kernel therefore:
//
//  1) EPSP conv: fold taps oldest-first (lag 99 -> 0) with single fp32
//     accumulator starting at 0 — matching cuDNN implicit-GEMM's ascending-K
//     FFMA chain over the (pre-flipped) kernel. Zero-input taps are exact
//     no-ops in an FMA chain, so only set bits are folded (input is binary,
//     tracked in a 128-bit shift register). Taps come verbatim from d_in[1].
//  2) Refractory: reference scan keeps buf[100]; each slot is a chronological
//     fold of acc = fl(acc + fl(n*rs[k])) (XLA: separate mul and add).
//     Implemented as a register ring of 50 packed f32x2 pairs with static
//     mod-100 indexing (full 100-step unroll); every step updates all 50
//     pairs with mul.rn.f32x2 + add.rn.f32x2 (per-lane rounding == scalar).
//     rs[99] = 0 makes the update uniform. Two alignment-shifted smem tap
//     tables (RSA/RSB) give aligned, warp-uniform (broadcast) LDS.64.
//  3) Spike fn: op-for-op — floorf(fmaxf(v,0)), expf(-2|v-1|) [libdevice],
//     sg=2*e, term=sg*v, out=fl(fl(n-term)+term); buf update uses out.

#define T_STEPS 1024
#define BATCH   16
#define NSYN    2
#define NNEU    2048
#define BN      (BATCH * NNEU)          // 32768 neurons
#define TSTRIDE (BATCH * NSYN * NNEU)   // 65536 floats per timestep
#define PF      4                       // prefetch depth (divides 100 and 24)

__global__ __launch_bounds__(128)
void spiking_layer_exact(const float* __restrict__ in,
                         const float* __restrict__ epsp,   // (2, 100)
                         const float* __restrict__ refk,   // (100,)
                         float* __restrict__ out)
{
    __shared__ __align__(8) float K0[100];   // epsp taps syn0, by lag
    __shared__ __align__(8) float K1[100];   // epsp taps syn1, by lag
    __shared__ __align__(8) float RSA[100];  // rs[k] = -refk[k+1], rs[99]=0
    __shared__ __align__(8) float RSB[100];  // RSB[j] = rs[(j+1)%100]

    const int tid = threadIdx.x;
    for (int j = tid; j < 100; j += 128) {
        K0[j] = epsp[j];
        K1[j] = epsp[100 + j];
        RSA[j] = (j < 99) ? -refk[j + 1] : 0.0f;
    }
    __syncthreads();
    for (int j = tid; j < 100; j += 128) RSB[j] = RSA[(j + 1) % 100];
    __syncthreads();

    const unsigned long long* RSA64 = (const unsigned long long*)RSA;
    const unsigned long long* RSB64 = (const unsigned long long*)RSB;

    const int g = blockIdx.x * 128 + tid;       // neuron id in [0, BN)
    const int b = g >> 11;
    const int n = g & (NNEU - 1);
    const float* p0 = in + (size_t)b * (NSYN * NNEU) + n;  // synapse 0
    const float* p1 = p0 + NNEU;                            // synapse 1
    float* po = out + g;

    // refractory buffer: 100 slots as 50 packed f32x2 pairs (lo = even slot)
    unsigned long long bufp[50];
#pragma unroll
    for (int m = 0; m < 50; m++) bufp[m] = 0ull;

    // 128-bit spike history per synapse; after insert, bit j = x[t-j]
    unsigned long long h0lo = 0ull, h0hi = 0ull;
    unsigned long long h1lo = 0ull, h1hi = 0ull;

    float x0b[PF], x1b[PF];
#pragma unroll
    for (int i = 0; i < PF; i++) {
        x0b[i] = __ldcs(p0 + (size_t)i * TSTRIDE);
        x1b[i] = __ldcs(p1 + (size_t)i * TSTRIDE);
    }

    auto step = [&](int t, int c) {
        const int i4 = c & (PF - 1);
        const float x0 = x0b[i4];
        const float x1 = x1b[i4];
        if (t + PF < T_STEPS) {
            x0b[i4] = __ldcs(p0 + (size_t)(t + PF) * TSTRIDE);
            x1b[i4] = __ldcs(p1 + (size_t)(t + PF) * TSTRIDE);
        }

        // insert current spikes (input exactly 0.0f / 1.0f)
        h0hi = (h0hi << 1) | (h0lo >> 63); h0lo = (h0lo << 1) | (unsigned long long)(x0 != 0.0f);
        h1hi = (h1hi << 1) | (h1lo >> 63); h1lo = (h1lo << 1) | (unsigned long long)(x1 != 0.0f);

        // EPSP conv: fold set taps oldest-first (lag 99 -> 0), plain FADD.
        float c0 = 0.0f, c1 = 0.0f;
        {
            unsigned long long w = h0hi & 0xFFFFFFFFFull;   // lags 64..99
            while (w) { int bb = 63 - __clzll(w); w ^= (1ull << bb); c0 = __fadd_rn(c0, K0[64 + bb]); }
            w = h0lo;                                        // lags 0..63
            while (w) { int bb = 63 - __clzll(w); w ^= (1ull << bb); c0 = __fadd_rn(c0, K0[bb]); }
        }
        {
            unsigned long long w = h1hi & 0xFFFFFFFFFull;
            while (w) { int bb = 63 - __clzll(w); w ^= (1ull << bb); c1 = __fadd_rn(c1, K1[64 + bb]); }
            w = h1lo;
            while (w) { int bb = 63 - __clzll(w); w ^= (1ull << bb); c1 = __fadd_rn(c1, K1[bb]); }
        }
        const float vt = __fadd_rn(c0, c1);   // vmem_syn.sum(axis=1)

        // read refractory accumulator for this step (slot c)
        float bacc;
        {
            unsigned long long pr = bufp[c >> 1];
            unsigned int u = (c & 1) ? (unsigned int)(pr >> 32) : (unsigned int)pr;
            bacc = __uint_as_float(u);
        }
        const float v = __fadd_rn(vt, bacc);  // v_eff = v_t + buf[0]

        // spike function, op-for-op vs reference
        const float nf   = floorf(fmaxf(v, 0.0f));
        const float e    = expf(__fmul_rn(fabsf(__fadd_rn(v, -1.0f)), -2.0f));
        const float sg   = __fmul_rn(2.0f, e);
        const float term = __fmul_rn(sg, v);
        const float nout = __fadd_rn(__fadd_rn(nf, -term), term);

        __stcs(po + (size_t)t * BN, nout);

        // zero slot c (it becomes the slot for time t+100; rs[99]=0)
        bufp[c >> 1] &= (c & 1) ? 0x00000000FFFFFFFFull : 0xFFFFFFFF00000000ull;

        // buf update: slot s gets += fl(nout * rs[(s-c-1) mod 100]),
        // as packed f32x2 (per-lane rounding identical to scalar mul+add).
        unsigned long long n2;
        asm("mov.b64 %0, {%1, %2};" : "=l"(n2) : "f"(nout), "f"(nout));
#pragma unroll
        for (int m = 0; m < 50; ++m) {
            const int k0 = (2 * m - c - 1 + 200) % 100;   // k for even slot 2m
            unsigned long long rs2;
            if (c & 1) rs2 = RSA64[k0 >> 1];              // k0 even: (rs[k0], rs[k0+1])
            else       rs2 = RSB64[(k0 - 1) >> 1];        // k0 odd via shifted table
            unsigned long long p2, nb;
            asm("mul.rn.f32x2 %0, %1, %2;" : "=l"(p2) : "l"(n2), "l"(rs2));
            asm("add.rn.f32x2 %0, %1, %2;" : "=l"(nb) : "l"(bufp[m]), "l"(p2));
            bufp[m] = nb;
        }
    };

#pragma unroll 1
    for (int blk = 0; blk < 10; ++blk) {
        const int tb = blk * 100;
#pragma unroll
        for (int i = 0; i < 100; ++i) step(tb + i, i);
    }
#pragma unroll
    for (int i = 0; i < 24; ++i) step(1000 + i, i);
}

extern "C" void kernel_launch(void* const* d_in, const int* in_sizes, int n_in,
                              void* d_out, int out_size)
{
    const float* spikes = (const float*)d_in[0];
    const float* epsp   = (const float*)d_in[1];
    const float* refk   = (const float*)d_in[2];
    float* out = (float*)d_out;

    spiking_layer_exact<<<BN / 128, 128>>>(spikes, epsp, refk, out);
}